// round 1
// baseline (speedup 1.0000x reference)
#include <cuda_runtime.h>
#include <math.h>

// ---------------------------------------------------------------------------
// Fixed problem shape
// ---------------------------------------------------------------------------
constexpr int B_  = 8;
constexpr int N_  = 1024;
constexpr int H_  = 768;
constexpr int NH_ = 12;
constexpr int AS_ = 64;
constexpr int MO_ = 256;
constexpr int H2_ = 2 * H_;
constexpr float SCALE_ = 0.125f;     // 64^-0.5
constexpr float SLOPE_ = 0.02f;      // leaky relu slope

// ---------------------------------------------------------------------------
// Scratch (static device globals; no runtime allocation)
// ---------------------------------------------------------------------------
__device__ float g_varin[B_ * N_ * H_];
__device__ float g_f1[B_ * N_ * H_];     // var_feat
__device__ float g_f2[B_ * N_ * H_];     // sym_feat
__device__ float g_q[B_ * N_ * H_];
__device__ float g_k[B_ * N_ * H_];
__device__ float g_v[B_ * N_ * H_];
__device__ float g_y[B_ * N_ * H_];      // attention output (pre W_o)
__device__ float g_yo[B_ * N_ * H_];     // after W_o
__device__ float g_s[B_ * N_];           // edge scores
__device__ float g_AG[B_ * N_ * N_];
__device__ float g_VG[B_ * N_ * N_];
__device__ float g_BIAS[B_ * N_ * N_];   // 0.2AG + 0.8 AG@AG + VG@VG
__device__ float g_att[(long long)B_ * NH_ * N_ * N_];  // 402 MB logits/probs
__device__ float g_cbar[B_ * H2_];
__device__ float g_pm[B_ * H_];

// ---------------------------------------------------------------------------
// K1: build var_in
// ---------------------------------------------------------------------------
__global__ void k_varin(const float* __restrict__ x, const int* __restrict__ pp)
{
    int idx = blockIdx.x * blockDim.x + threadIdx.x;
    if (idx >= B_ * N_ * H_) return;
    int h  = idx % H_;
    int bn = idx / H_;
    int i  = bn % N_;
    int b  = bn / N_;
    bool single = (i == 0) || (i >= 2 && pp[b * N_ + i - 2] == 1);
    float xn = x[((long long)b * N_ + ((i + 1) & (N_ - 1))) * H_ + h];
    float out;
    if (single) {
        out = xn;
    } else {
        float xp = x[((long long)b * N_ + ((i - 1) & (N_ - 1))) * H_ + h];
        out = 0.5f * (xp + xn);
    }
    g_varin[idx] = out;
}

// ---------------------------------------------------------------------------
// Generic fp32 SGEMM, compile-time op selection (epilogue + operand wiring)
// ---------------------------------------------------------------------------
constexpr int OP_VAR = 0, OP_SYM = 1, OP_Q = 2, OP_K = 3, OP_V = 4, OP_O = 5,
              OP_AGAG = 6, OP_VGVG = 7, OP_SC = 8, OP_PV = 9;

template<int OP, int BM, int BN, int BK, int TM, int TN>
__global__ __launch_bounds__((BM / TM) * (BN / TN))
void k_gemm(const float* __restrict__ P0, const float* __restrict__ P1,
            const float* __restrict__ P2)
{
    constexpr int THREADS = (BM / TM) * (BN / TN);
    constexpr bool TRANSB = (OP == OP_VAR || OP == OP_SYM || OP == OP_Q ||
                             OP == OP_K   || OP == OP_V   || OP == OP_O ||
                             OP == OP_SC);

    const int z = blockIdx.z;
    const float* A;  const float* Bp;  float* C;  const float* X = nullptr;
    int lda, ldb, ldc, ldx = 0, K;

    if constexpr (OP == OP_VAR) { A = g_varin; Bp = P0; X = P1; C = g_f1; lda = ldb = ldc = H_; K = H_; }
    else if constexpr (OP == OP_SYM) { A = P2; Bp = P0; X = P1; C = g_f2; lda = ldb = ldc = H_; K = H_; }
    else if constexpr (OP == OP_Q)   { A = P2; Bp = P0; X = P1; C = g_q;  lda = ldb = ldc = H_; K = H_; }
    else if constexpr (OP == OP_K)   { A = P2; Bp = P0; X = P1; C = g_k;  lda = ldb = ldc = H_; K = H_; }
    else if constexpr (OP == OP_V)   { A = P2; Bp = P0; X = P1; C = g_v;  lda = ldb = ldc = H_; K = H_; }
    else if constexpr (OP == OP_O)   { A = g_y; Bp = P0; X = P1; C = g_yo; lda = ldb = ldc = H_; K = H_; }
    else if constexpr (OP == OP_AGAG) {
        long long off = (long long)z * N_ * N_;
        A = g_AG + off; Bp = g_AG + off; X = g_AG + off; C = g_BIAS + off;
        lda = ldb = ldc = ldx = N_; K = N_;
    }
    else if constexpr (OP == OP_VGVG) {
        long long off = (long long)z * N_ * N_;
        A = g_VG + off; Bp = g_VG + off; C = g_BIAS + off;
        lda = ldb = ldc = N_; K = N_;
    }
    else if constexpr (OP == OP_SC) {
        int b = z / NH_, h = z % NH_;
        A  = g_q   + (long long)b * N_ * H_ + h * AS_;
        Bp = g_k   + (long long)b * N_ * H_ + h * AS_;
        C  = g_att + (long long)z * N_ * N_;
        X  = g_BIAS + (long long)b * N_ * N_;
        lda = ldb = H_; ldc = N_; ldx = N_; K = AS_;
    }
    else { // OP_PV
        int b = z / NH_, h = z % NH_;
        A  = g_att + (long long)z * N_ * N_;
        Bp = g_v   + (long long)b * N_ * H_ + h * AS_;
        C  = g_y   + (long long)b * N_ * H_ + h * AS_;
        lda = N_; ldb = ldc = H_; K = N_;
    }

    __shared__ float As[BK][BM + 1];
    __shared__ float Bs[BK][BN + 1];

    const int row0 = blockIdx.y * BM;
    const int col0 = blockIdx.x * BN;
    const int tid  = threadIdx.x;
    const int tr   = tid / (BN / TN);
    const int tc   = tid % (BN / TN);

    float acc[TM][TN];
#pragma unroll
    for (int i = 0; i < TM; i++)
#pragma unroll
        for (int j = 0; j < TN; j++) acc[i][j] = 0.f;

    for (int k0 = 0; k0 < K; k0 += BK) {
#pragma unroll
        for (int i = tid; i < BM * BK; i += THREADS) {
            int m = i / BK, kk = i % BK;
            As[kk][m] = A[(long long)(row0 + m) * lda + (k0 + kk)];
        }
        if constexpr (!TRANSB) {
#pragma unroll
            for (int i = tid; i < BK * BN; i += THREADS) {
                int n = i % BN, kk = i / BN;
                Bs[kk][n] = Bp[(long long)(k0 + kk) * ldb + (col0 + n)];
            }
        } else {
#pragma unroll
            for (int i = tid; i < BK * BN; i += THREADS) {
                int kk = i % BK, n = i / BK;
                Bs[kk][n] = Bp[(long long)(col0 + n) * ldb + (k0 + kk)];
            }
        }
        __syncthreads();
#pragma unroll
        for (int kk = 0; kk < BK; kk++) {
            float ra[TM], rb[TN];
#pragma unroll
            for (int i = 0; i < TM; i++) ra[i] = As[kk][tr * TM + i];
#pragma unroll
            for (int j = 0; j < TN; j++) rb[j] = Bs[kk][tc * TN + j];
#pragma unroll
            for (int i = 0; i < TM; i++)
#pragma unroll
                for (int j = 0; j < TN; j++)
                    acc[i][j] = fmaf(ra[i], rb[j], acc[i][j]);
        }
        __syncthreads();
    }

#pragma unroll
    for (int i = 0; i < TM; i++) {
        int gm = row0 + tr * TM + i;
#pragma unroll
        for (int j = 0; j < TN; j++) {
            int gn = col0 + tc * TN + j;
            float v = acc[i][j];
            if constexpr (OP <= OP_O)           v += X[gn];                              // +bias vec
            else if constexpr (OP == OP_AGAG)   v = 0.2f * X[(long long)gm * ldx + gn] + 0.8f * v;
            else if constexpr (OP == OP_VGVG)   v = C[(long long)gm * ldc + gn] + v;     // BIAS += VG@VG
            else if constexpr (OP == OP_SC)     v = SCALE_ * v + X[(long long)gm * ldx + gn];
            C[(long long)gm * ldc + gn] = v;
        }
    }
}

// ---------------------------------------------------------------------------
// K4: edge scores  s = lrelu( sum tanh(f1)*ws[:H] + tanh(f2)*ws[H:] + b )
// ---------------------------------------------------------------------------
__global__ void k_score(const float* __restrict__ wsc, const float* __restrict__ bsc)
{
    int row = blockIdx.x;                 // over B*N
    int t = threadIdx.x;                  // 256
    const float* f1 = g_f1 + (long long)row * H_;
    const float* f2 = g_f2 + (long long)row * H_;
    float p = 0.f;
    for (int h = t; h < H_; h += 256)
        p += tanhf(f1[h]) * wsc[h] + tanhf(f2[h]) * wsc[H_ + h];
    __shared__ float red[256];
    red[t] = p; __syncthreads();
    for (int s = 128; s > 0; s >>= 1) { if (t < s) red[t] += red[t + s]; __syncthreads(); }
    if (t == 0) {
        float v = red[0] + bsc[0];
        g_s[row] = (v >= 0.f) ? v : SLOPE_ * v;
    }
}

// ---------------------------------------------------------------------------
// Copy input graphs into scratch
// ---------------------------------------------------------------------------
__global__ void k_copy2(const float* __restrict__ ag, const float* __restrict__ vg)
{
    long long idx = (long long)blockIdx.x * blockDim.x + threadIdx.x;
    long long tot = (long long)B_ * N_ * N_;
    if (idx < tot) { g_AG[idx] = ag[idx]; g_VG[idx] = vg[idx]; }
}

// ---------------------------------------------------------------------------
// Scatter edge scores into AG
// ---------------------------------------------------------------------------
__global__ void k_scatterAG(const int* __restrict__ pp)
{
    int t = blockIdx.x * blockDim.x + threadIdx.x;
    if (t >= B_ * N_) return;
    int i = t % N_, b = t / N_;
    if (pp[t] != 1) return;
    float sv = g_s[t];
    bool single = (i == 0) || (i >= 2 && pp[b * N_ + i - 2] == 1);
    float* AG = g_AG + (long long)b * N_ * N_;
    if (i >= 1) {                         // lower
        atomicAdd(&AG[(long long)(i - 1) * N_ + i], sv);
        atomicAdd(&AG[(long long)i * N_ + (i - 1)], sv);
    }
    if (i <= 1 || !single) {              // upper
        int ip = min(i + 1, N_ - 1);
        atomicAdd(&AG[(long long)i * N_ + ip], sv);
        atomicAdd(&AG[(long long)ip * N_ + i], sv);
    }
}

// ---------------------------------------------------------------------------
// Cross-occurrence scores into VG
// ---------------------------------------------------------------------------
__global__ void k_cross(const float* __restrict__ x, const float* __restrict__ wc,
                        const float* __restrict__ bc, const int* __restrict__ occ)
{
    int bm = blockIdx.x;                  // over B*MO
    int b = bm / MO_;
    int o0 = occ[bm * 2 + 0], o1 = occ[bm * 2 + 1];
    int t = threadIdx.x;                  // 256
    const float* x0 = x + ((long long)b * N_ + o0) * H_;
    const float* x1 = x + ((long long)b * N_ + o1) * H_;
    float p = 0.f;
    for (int h = t; h < H_; h += 256) p += 0.5f * (x0[h] + x1[h]) * wc[h];
    __shared__ float red[256];
    red[t] = p; __syncthreads();
    for (int s = 128; s > 0; s >>= 1) { if (t < s) red[t] += red[t + s]; __syncthreads(); }
    if (t == 0) {
        float v = red[0] + bc[0];
        float sc = (v >= 0.f) ? v : SLOPE_ * v;
        float* VG = g_VG + (long long)b * N_ * N_;
        atomicAdd(&VG[(long long)o0 * N_ + o1], sc);
        atomicAdd(&VG[(long long)o1 * N_ + o0], sc);
    }
}

// ---------------------------------------------------------------------------
// Row softmax over g_att (rows of length N_, float4 per thread)
// ---------------------------------------------------------------------------
__global__ void k_softmax()
{
    long long row = blockIdx.x;           // over B*NH*N
    float4* p = reinterpret_cast<float4*>(g_att + row * N_);
    int t = threadIdx.x, lane = t & 31, w = t >> 5;
    __shared__ float sred[32];
    float4 v = p[t];
    float m = fmaxf(fmaxf(v.x, v.y), fmaxf(v.z, v.w));
#pragma unroll
    for (int o = 16; o; o >>= 1) m = fmaxf(m, __shfl_xor_sync(0xffffffffu, m, o));
    if (lane == 0) sred[w] = m;
    __syncthreads();
    if (t < 32) {
        float mm = (t < 8) ? sred[t] : -3.4e38f;
#pragma unroll
        for (int o = 4; o; o >>= 1) mm = fmaxf(mm, __shfl_xor_sync(0xffffffffu, mm, o));
        if (t == 0) sred[0] = mm;
    }
    __syncthreads();
    m = sred[0];
    __syncthreads();
    v.x = __expf(v.x - m); v.y = __expf(v.y - m);
    v.z = __expf(v.z - m); v.w = __expf(v.w - m);
    float s = v.x + v.y + v.z + v.w;
#pragma unroll
    for (int o = 16; o; o >>= 1) s += __shfl_xor_sync(0xffffffffu, s, o);
    if (lane == 0) sred[w] = s;
    __syncthreads();
    if (t < 32) {
        float ss = (t < 8) ? sred[t] : 0.f;
#pragma unroll
        for (int o = 4; o; o >>= 1) ss += __shfl_xor_sync(0xffffffffu, ss, o);
        if (t == 0) sred[0] = ss;
    }
    __syncthreads();
    float inv = 1.f / sred[0];
    v.x *= inv; v.y *= inv; v.z *= inv; v.w *= inv;
    p[t] = v;
}

// ---------------------------------------------------------------------------
// Weighted mean of concat([var_y, yo]) over tokens  ->  g_cbar [B, 2H]
// ---------------------------------------------------------------------------
__global__ void k_cbar(const int* __restrict__ pp)
{
    int b = blockIdx.x;
    int c = blockIdx.y * 256 + threadIdx.x;   // 0..1535
    int t = threadIdx.x;
    __shared__ float wbuf[N_];
    __shared__ unsigned char sbuf[N_];
    __shared__ float wsumsh;
    for (int n = t; n < N_; n += 256) {
        int ppv = pp[b * N_ + n];
        bool pred   = (ppv == 1);
        bool single = (n == 0) || (n >= 2 && pp[b * N_ + n - 2] == 1);
        bool upper  = pred && (n <= 1 || !single);
        bool triple = upper && (n >= 1);
        wbuf[n] = pred ? (triple ? 3.f : 2.f) : 0.f;
        sbuf[n] = single ? 1 : 0;
    }
    __syncthreads();
    if (t == 0) { float s = 0.f; for (int n = 0; n < N_; n++) s += wbuf[n]; wsumsh = s; }
    __syncthreads();
    const float* Y = g_yo + (long long)b * N_ * H_;
    float acc = 0.f;
    if (c < H_) {
        for (int n = 0; n < N_; n++) {
            float w = wbuf[n]; if (w == 0.f) continue;
            float yn = Y[(long long)((n + 1) & (N_ - 1)) * H_ + c];
            float val = sbuf[n] ? yn
                                : 0.5f * (Y[(long long)((n - 1) & (N_ - 1)) * H_ + c] + yn);
            acc += w * val;
        }
    } else {
        int cc = c - H_;
        for (int n = 0; n < N_; n++) {
            float w = wbuf[n]; if (w == 0.f) continue;
            acc += w * Y[(long long)n * H_ + cc];
        }
    }
    g_cbar[b * H2_ + c] = acc / wsumsh;
}

// ---------------------------------------------------------------------------
// pm = cbar @ W_atom^T + b_atom   (tiny GEMM, one block per batch)
// ---------------------------------------------------------------------------
__global__ void k_pm(const float* __restrict__ Wa, const float* __restrict__ ba)
{
    int b = blockIdx.x;
    int t = threadIdx.x;                  // 768
    __shared__ float cb[H2_];
    for (int k = t; k < H2_; k += H_) cb[k] = g_cbar[b * H2_ + k];
    __syncthreads();
    const float* wr = Wa + (long long)t * H2_;
    float acc = 0.f;
    for (int k = 0; k < H2_; k++) acc += cb[k] * wr[k];
    g_pm[b * H_ + t] = acc + ba[t];
}

// ---------------------------------------------------------------------------
// Broadcast pm to output [B, N, H]
// ---------------------------------------------------------------------------
__global__ void k_bcast(float* __restrict__ out)
{
    int idx = blockIdx.x * blockDim.x + threadIdx.x;
    if (idx >= B_ * N_ * H_) return;
    int h = idx % H_;
    int b = idx / (N_ * H_);
    out[idx] = g_pm[b * H_ + h];
}

// ---------------------------------------------------------------------------
// Launch
// ---------------------------------------------------------------------------
extern "C" void kernel_launch(void* const* d_in, const int* in_sizes, int n_in,
                              void* d_out, int out_size)
{
    const float* x       = (const float*)d_in[0];
    const float* ag_in   = (const float*)d_in[1];
    const float* vg_in   = (const float*)d_in[2];
    const float* W_var   = (const float*)d_in[3];  const float* b_var  = (const float*)d_in[4];
    const float* W_sym   = (const float*)d_in[5];  const float* b_sym  = (const float*)d_in[6];
    const float* W_score = (const float*)d_in[7];  const float* b_score= (const float*)d_in[8];
    const float* W_cross = (const float*)d_in[9];  const float* b_cross= (const float*)d_in[10];
    const float* W_atom  = (const float*)d_in[11]; const float* b_atom = (const float*)d_in[12];
    const float* W_q     = (const float*)d_in[13]; const float* b_q    = (const float*)d_in[14];
    const float* W_k     = (const float*)d_in[15]; const float* b_k    = (const float*)d_in[16];
    const float* W_v     = (const float*)d_in[17]; const float* b_v    = (const float*)d_in[18];
    const float* W_o     = (const float*)d_in[19]; const float* b_o    = (const float*)d_in[20];
    const int*   pp      = (const int*)d_in[21];
    const int*   occ     = (const int*)d_in[24];
    float* out = (float*)d_out;

    const int tot = B_ * N_ * H_;

    // var_in
    k_varin<<<(tot + 255) / 256, 256>>>(x, pp);

    // linear layers for edge scoring
    dim3 gl(H_ / 128, (B_ * N_) / 128, 1);
    k_gemm<OP_VAR, 128, 128, 16, 8, 8><<<gl, 256>>>(W_var, b_var, nullptr);
    k_gemm<OP_SYM, 128, 128, 16, 8, 8><<<gl, 256>>>(W_sym, b_sym, x);
    k_score<<<B_ * N_, 256>>>(W_score, b_score);

    // graphs
    k_copy2<<<(B_ * N_ * N_ + 255) / 256, 256>>>(ag_in, vg_in);
    k_scatterAG<<<(B_ * N_ + 255) / 256, 256>>>(pp);
    k_cross<<<B_ * MO_, 256>>>(x, W_cross, b_cross, occ);

    // q, k, v projections
    k_gemm<OP_Q, 128, 128, 16, 8, 8><<<gl, 256>>>(W_q, b_q, x);
    k_gemm<OP_K, 128, 128, 16, 8, 8><<<gl, 256>>>(W_k, b_k, x);
    k_gemm<OP_V, 128, 128, 16, 8, 8><<<gl, 256>>>(W_v, b_v, x);

    // BIAS = 0.2*AG + 0.8*AG@AG ; BIAS += VG@VG
    dim3 gg(N_ / 128, N_ / 128, B_);
    k_gemm<OP_AGAG, 128, 128, 16, 8, 8><<<gg, 256>>>(nullptr, nullptr, nullptr);
    k_gemm<OP_VGVG, 128, 128, 16, 8, 8><<<gg, 256>>>(nullptr, nullptr, nullptr);

    // attention logits, softmax, PV
    dim3 gs(N_ / 128, N_ / 128, B_ * NH_);
    k_gemm<OP_SC, 128, 128, 16, 8, 8><<<gs, 256>>>(nullptr, nullptr, nullptr);
    k_softmax<<<B_ * NH_ * N_, 256>>>();
    dim3 gp(1, N_ / 64, B_ * NH_);
    k_gemm<OP_PV, 64, 64, 16, 4, 4><<<gp, 256>>>(nullptr, nullptr, nullptr);

    // output projection
    k_gemm<OP_O, 128, 128, 16, 8, 8><<<gl, 256>>>(W_o, b_o, nullptr);

    // path embedding (affine trick: weighted-mean before W_atom)
    dim3 gc(B_, H2_ / 256);
    k_cbar<<<gc, 256>>>(pp);
    k_pm<<<B_, H_>>>(W_atom, b_atom);
    k_bcast<<<(tot + 255) / 256, 256>>>(out);
}

// round 5
// speedup vs baseline: 2.3636x; 2.3636x over previous
#include <cuda_runtime.h>
#include <math.h>
#include <stdint.h>

// ---------------------------------------------------------------------------
// Fixed problem shape
// ---------------------------------------------------------------------------
constexpr int B_  = 8;
constexpr int N_  = 1024;
constexpr int H_  = 768;
constexpr int NH_ = 12;
constexpr int AS_ = 64;
constexpr int MO_ = 256;
constexpr int H2_ = 2 * H_;
constexpr float SCALE_ = 0.125f;     // 64^-0.5
constexpr float SLOPE_ = 0.02f;      // leaky relu slope

// ---------------------------------------------------------------------------
// Scratch (static device globals; no runtime allocation)
// ---------------------------------------------------------------------------
__device__ float g_varin[B_ * N_ * H_];
__device__ float g_f1[B_ * N_ * H_];     // var_feat
__device__ float g_f2[B_ * N_ * H_];     // sym_feat
__device__ float g_q[B_ * N_ * H_];
__device__ float g_k[B_ * N_ * H_];
__device__ float g_v[B_ * N_ * H_];
__device__ float g_y[B_ * N_ * H_];      // attention output (pre W_o)
__device__ float g_yo[B_ * N_ * H_];     // after W_o
__device__ float g_s[B_ * N_];           // edge scores
__device__ float g_AG[B_ * N_ * N_];
__device__ float g_VG[B_ * N_ * N_];
__device__ float g_BIAS[B_ * N_ * N_];   // 0.2AG + 0.8 AG@AG + VG@VG
__device__ float g_att[(long long)B_ * NH_ * N_ * N_];  // 402 MB logits/probs
__device__ float g_cbar[B_ * H2_];
__device__ float g_pm[B_ * H_];

// ---------------------------------------------------------------------------
// tf32 helpers
// ---------------------------------------------------------------------------
__device__ __forceinline__ uint32_t f2tf(float f) {
    uint32_t r; asm("cvt.rna.tf32.f32 %0, %1;" : "=r"(r) : "f"(f)); return r;
}
__device__ __forceinline__ void mma8(float* c, const uint32_t* a, const uint32_t* b) {
    asm volatile("mma.sync.aligned.m16n8k8.row.col.f32.tf32.tf32.f32 "
        "{%0,%1,%2,%3}, {%4,%5,%6,%7}, {%8,%9}, {%0,%1,%2,%3};"
        : "+f"(c[0]), "+f"(c[1]), "+f"(c[2]), "+f"(c[3])
        : "r"(a[0]), "r"(a[1]), "r"(a[2]), "r"(a[3]), "r"(b[0]), "r"(b[1]));
}

// ---------------------------------------------------------------------------
// K1: build var_in
// ---------------------------------------------------------------------------
__global__ void k_varin(const float* __restrict__ x, const int* __restrict__ pp)
{
    int idx = blockIdx.x * blockDim.x + threadIdx.x;
    if (idx >= B_ * N_ * H_) return;
    int h  = idx % H_;
    int bn = idx / H_;
    int i  = bn % N_;
    int b  = bn / N_;
    bool single = (i == 0) || (i >= 2 && pp[b * N_ + i - 2] == 1);
    float xn = x[((long long)b * N_ + ((i + 1) & (N_ - 1))) * H_ + h];
    float out;
    if (single) {
        out = xn;
    } else {
        float xp = x[((long long)b * N_ + ((i - 1) & (N_ - 1))) * H_ + h];
        out = 0.5f * (xp + xn);
    }
    g_varin[idx] = out;
}

// ---------------------------------------------------------------------------
// tf32 tensor-core GEMM, compile-time op selection (epilogue + operand wiring)
// ---------------------------------------------------------------------------
constexpr int OP_VAR = 0, OP_SYM = 1, OP_Q = 2, OP_K = 3, OP_V = 4, OP_O = 5,
              OP_AGAG = 6, OP_VGVG = 7, OP_SC = 8, OP_PV = 9;

template<int OP, int BM, int BN, int BK, int WM, int WN>
__global__ __launch_bounds__((BM / WM) * (BN / WN) * 32)
void k_mma(const float* __restrict__ P0, const float* __restrict__ P1,
           const float* __restrict__ P2)
{
    constexpr bool TRANSB = (OP == OP_VAR || OP == OP_SYM || OP == OP_Q ||
                             OP == OP_K   || OP == OP_V   || OP == OP_O ||
                             OP == OP_SC);
    constexpr int WARPS_M = BM / WM, WARPS_N = BN / WN;
    constexpr int THREADS = WARPS_M * WARPS_N * 32;
    constexpr int MT = WM / 16, NT = WN / 8;
    constexpr int BROWS = TRANSB ? BN : BK;
    constexpr int BCOLS = TRANSB ? (BK + 4) : (BN + 8);

    const int z = blockIdx.z;
    const float* A;  const float* Bp;  float* C;  const float* X = nullptr;
    int lda, ldb, ldc, ldx = 0, K;

    if constexpr (OP == OP_VAR) { A = g_varin; Bp = P0; X = P1; C = g_f1; lda = ldb = ldc = H_; K = H_; }
    else if constexpr (OP == OP_SYM) { A = P2; Bp = P0; X = P1; C = g_f2; lda = ldb = ldc = H_; K = H_; }
    else if constexpr (OP == OP_Q)   { A = P2; Bp = P0; X = P1; C = g_q;  lda = ldb = ldc = H_; K = H_; }
    else if constexpr (OP == OP_K)   { A = P2; Bp = P0; X = P1; C = g_k;  lda = ldb = ldc = H_; K = H_; }
    else if constexpr (OP == OP_V)   { A = P2; Bp = P0; X = P1; C = g_v;  lda = ldb = ldc = H_; K = H_; }
    else if constexpr (OP == OP_O)   { A = g_y; Bp = P0; X = P1; C = g_yo; lda = ldb = ldc = H_; K = H_; }
    else if constexpr (OP == OP_AGAG) {
        long long off = (long long)z * N_ * N_;
        A = g_AG + off; Bp = g_AG + off; X = g_AG + off; C = g_BIAS + off;
        lda = ldb = ldc = ldx = N_; K = N_;
    }
    else if constexpr (OP == OP_VGVG) {
        long long off = (long long)z * N_ * N_;
        A = g_VG + off; Bp = g_VG + off; C = g_BIAS + off;
        lda = ldb = ldc = N_; K = N_;
    }
    else if constexpr (OP == OP_SC) {
        int b = z / NH_, h = z % NH_;
        A  = g_q   + (long long)b * N_ * H_ + h * AS_;
        Bp = g_k   + (long long)b * N_ * H_ + h * AS_;
        C  = g_att + (long long)z * N_ * N_;
        X  = g_BIAS + (long long)b * N_ * N_;
        lda = ldb = H_; ldc = N_; ldx = N_; K = AS_;
    }
    else { // OP_PV
        int b = z / NH_, h = z % NH_;
        A  = g_att + (long long)z * N_ * N_;
        Bp = g_v   + (long long)b * N_ * H_ + h * AS_;
        C  = g_y   + (long long)b * N_ * H_ + h * AS_;
        lda = N_; ldb = ldc = H_; K = N_;
    }

    __shared__ uint32_t As[BM][BK + 4];
    __shared__ uint32_t Bs[BROWS][BCOLS];

    const int tid  = threadIdx.x;
    const int wid  = tid >> 5, lane = tid & 31;
    const int g    = lane >> 2, t4 = lane & 3;
    const int wm   = (wid / WARPS_N) * WM;
    const int wn   = (wid % WARPS_N) * WN;
    const int row0 = blockIdx.y * BM;
    const int col0 = blockIdx.x * BN;

    float acc[MT][NT][4] = {};

    for (int k0 = 0; k0 < K; k0 += BK) {
        // A tile -> As[m][k] (m-major, stride BK+4), tf32-converted
#pragma unroll
        for (int i = tid; i < BM * (BK / 4); i += THREADS) {
            int m = i / (BK / 4), kq = (i % (BK / 4)) * 4;
            const float4 v = *reinterpret_cast<const float4*>(
                &A[(long long)(row0 + m) * lda + k0 + kq]);
            uint4 u = make_uint4(f2tf(v.x), f2tf(v.y), f2tf(v.z), f2tf(v.w));
            *reinterpret_cast<uint4*>(&As[m][kq]) = u;
        }
        // B tile
        if constexpr (TRANSB) {
            // W[n][k] row-major -> Bs[n][k] (n-major)
#pragma unroll
            for (int i = tid; i < BN * (BK / 4); i += THREADS) {
                int n = i / (BK / 4), kq = (i % (BK / 4)) * 4;
                const float4 v = *reinterpret_cast<const float4*>(
                    &Bp[(long long)(col0 + n) * ldb + k0 + kq]);
                uint4 u = make_uint4(f2tf(v.x), f2tf(v.y), f2tf(v.z), f2tf(v.w));
                *reinterpret_cast<uint4*>(&Bs[n][kq]) = u;
            }
        } else {
            // B[k][n] row-major -> Bs[k][n] (k-major)
#pragma unroll
            for (int i = tid; i < BK * (BN / 4); i += THREADS) {
                int kk = i / (BN / 4), nq = (i % (BN / 4)) * 4;
                const float4 v = *reinterpret_cast<const float4*>(
                    &Bp[(long long)(k0 + kk) * ldb + col0 + nq]);
                uint4 u = make_uint4(f2tf(v.x), f2tf(v.y), f2tf(v.z), f2tf(v.w));
                *reinterpret_cast<uint4*>(&Bs[kk][nq]) = u;
            }
        }
        __syncthreads();

#pragma unroll
        for (int k8 = 0; k8 < BK / 8; k8++) {
            const int kk = k8 * 8;
            uint32_t af[MT][4], bf[NT][2];
#pragma unroll
            for (int it = 0; it < MT; it++) {
                int r = wm + it * 16 + g;
                af[it][0] = As[r][kk + t4];
                af[it][1] = As[r + 8][kk + t4];
                af[it][2] = As[r][kk + t4 + 4];
                af[it][3] = As[r + 8][kk + t4 + 4];
            }
#pragma unroll
            for (int jt = 0; jt < NT; jt++) {
                int n = wn + jt * 8 + g;
                if constexpr (TRANSB) {
                    bf[jt][0] = Bs[n][kk + t4];
                    bf[jt][1] = Bs[n][kk + t4 + 4];
                } else {
                    bf[jt][0] = Bs[kk + t4][n];
                    bf[jt][1] = Bs[kk + t4 + 4][n];
                }
            }
#pragma unroll
            for (int it = 0; it < MT; it++)
#pragma unroll
                for (int jt = 0; jt < NT; jt++)
                    mma8(acc[it][jt], af[it], bf[jt]);
        }
        __syncthreads();
    }

    // epilogue: each thread owns pairs of consecutive columns (float2 stores)
#pragma unroll
    for (int it = 0; it < MT; it++) {
#pragma unroll
        for (int jt = 0; jt < NT; jt++) {
#pragma unroll
            for (int half = 0; half < 2; half++) {
                int gm = row0 + wm + it * 16 + g + half * 8;
                int gn = col0 + wn + jt * 8 + 2 * t4;
                float v0 = acc[it][jt][half * 2 + 0];
                float v1 = acc[it][jt][half * 2 + 1];
                if constexpr (OP <= OP_O) {
                    v0 += X[gn]; v1 += X[gn + 1];
                } else if constexpr (OP == OP_AGAG) {
                    const float2 xo = *reinterpret_cast<const float2*>(&X[(long long)gm * ldx + gn]);
                    v0 = 0.2f * xo.x + 0.8f * v0;
                    v1 = 0.2f * xo.y + 0.8f * v1;
                } else if constexpr (OP == OP_VGVG) {
                    const float2 co = *reinterpret_cast<const float2*>(&C[(long long)gm * ldc + gn]);
                    v0 += co.x; v1 += co.y;
                } else if constexpr (OP == OP_SC) {
                    const float2 xo = *reinterpret_cast<const float2*>(&X[(long long)gm * ldx + gn]);
                    v0 = SCALE_ * v0 + xo.x;
                    v1 = SCALE_ * v1 + xo.y;
                }
                *reinterpret_cast<float2*>(&C[(long long)gm * ldc + gn]) = make_float2(v0, v1);
            }
        }
    }
}

// ---------------------------------------------------------------------------
// K4: edge scores  s = lrelu( sum tanh(f1)*ws[:H] + tanh(f2)*ws[H:] + b )
// ---------------------------------------------------------------------------
__global__ void k_score(const float* __restrict__ wsc, const float* __restrict__ bsc)
{
    int row = blockIdx.x;                 // over B*N
    int t = threadIdx.x;                  // 256
    const float* f1 = g_f1 + (long long)row * H_;
    const float* f2 = g_f2 + (long long)row * H_;
    float p = 0.f;
    for (int h = t; h < H_; h += 256)
        p += tanhf(f1[h]) * wsc[h] + tanhf(f2[h]) * wsc[H_ + h];
    __shared__ float red[256];
    red[t] = p; __syncthreads();
    for (int s = 128; s > 0; s >>= 1) { if (t < s) red[t] += red[t + s]; __syncthreads(); }
    if (t == 0) {
        float v = red[0] + bsc[0];
        g_s[row] = (v >= 0.f) ? v : SLOPE_ * v;
    }
}

// ---------------------------------------------------------------------------
// Copy input graphs into scratch (float4)
// ---------------------------------------------------------------------------
__global__ void k_copy2(const float4* __restrict__ ag, const float4* __restrict__ vg)
{
    long long idx = (long long)blockIdx.x * blockDim.x + threadIdx.x;
    long long tot = (long long)B_ * N_ * N_ / 4;
    if (idx < tot) {
        reinterpret_cast<float4*>(g_AG)[idx] = ag[idx];
        reinterpret_cast<float4*>(g_VG)[idx] = vg[idx];
    }
}

// ---------------------------------------------------------------------------
// Scatter edge scores into AG
// ---------------------------------------------------------------------------
__global__ void k_scatterAG(const int* __restrict__ pp)
{
    int t = blockIdx.x * blockDim.x + threadIdx.x;
    if (t >= B_ * N_) return;
    int i = t % N_, b = t / N_;
    if (pp[t] != 1) return;
    float sv = g_s[t];
    bool single = (i == 0) || (i >= 2 && pp[b * N_ + i - 2] == 1);
    float* AG = g_AG + (long long)b * N_ * N_;
    if (i >= 1) {                         // lower
        atomicAdd(&AG[(long long)(i - 1) * N_ + i], sv);
        atomicAdd(&AG[(long long)i * N_ + (i - 1)], sv);
    }
    if (i <= 1 || !single) {              // upper
        int ip = min(i + 1, N_ - 1);
        atomicAdd(&AG[(long long)i * N_ + ip], sv);
        atomicAdd(&AG[(long long)ip * N_ + i], sv);
    }
}

// ---------------------------------------------------------------------------
// Cross-occurrence scores into VG
// ---------------------------------------------------------------------------
__global__ void k_cross(const float* __restrict__ x, const float* __restrict__ wc,
                        const float* __restrict__ bc, const int* __restrict__ occ)
{
    int bm = blockIdx.x;                  // over B*MO
    int b = bm / MO_;
    int o0 = occ[bm * 2 + 0], o1 = occ[bm * 2 + 1];
    int t = threadIdx.x;                  // 256
    const float* x0 = x + ((long long)b * N_ + o0) * H_;
    const float* x1 = x + ((long long)b * N_ + o1) * H_;
    float p = 0.f;
    for (int h = t; h < H_; h += 256) p += 0.5f * (x0[h] + x1[h]) * wc[h];
    __shared__ float red[256];
    red[t] = p; __syncthreads();
    for (int s = 128; s > 0; s >>= 1) { if (t < s) red[t] += red[t + s]; __syncthreads(); }
    if (t == 0) {
        float v = red[0] + bc[0];
        float sc = (v >= 0.f) ? v : SLOPE_ * v;
        float* VG = g_VG + (long long)b * N_ * N_;
        atomicAdd(&VG[(long long)o0 * N_ + o1], sc);
        atomicAdd(&VG[(long long)o1 * N_ + o0], sc);
    }
}

// ---------------------------------------------------------------------------
// Row softmax over g_att (rows of length N_, float4 per thread)
// ---------------------------------------------------------------------------
__global__ void k_softmax()
{
    long long row = blockIdx.x;           // over B*NH*N
    float4* p = reinterpret_cast<float4*>(g_att + row * N_);
    int t = threadIdx.x, lane = t & 31, w = t >> 5;
    __shared__ float sred[32];
    float4 v = p[t];
    float m = fmaxf(fmaxf(v.x, v.y), fmaxf(v.z, v.w));
#pragma unroll
    for (int o = 16; o; o >>= 1) m = fmaxf(m, __shfl_xor_sync(0xffffffffu, m, o));
    if (lane == 0) sred[w] = m;
    __syncthreads();
    if (t < 32) {
        float mm = (t < 8) ? sred[t] : -3.4e38f;
#pragma unroll
        for (int o = 4; o; o >>= 1) mm = fmaxf(mm, __shfl_xor_sync(0xffffffffu, mm, o));
        if (t == 0) sred[0] = mm;
    }
    __syncthreads();
    m = sred[0];
    __syncthreads();
    v.x = __expf(v.x - m); v.y = __expf(v.y - m);
    v.z = __expf(v.z - m); v.w = __expf(v.w - m);
    float s = v.x + v.y + v.z + v.w;
#pragma unroll
    for (int o = 16; o; o >>= 1) s += __shfl_xor_sync(0xffffffffu, s, o);
    if (lane == 0) sred[w] = s;
    __syncthreads();
    if (t < 32) {
        float ss = (t < 8) ? sred[t] : 0.f;
#pragma unroll
        for (int o = 4; o; o >>= 1) ss += __shfl_xor_sync(0xffffffffu, ss, o);
        if (t == 0) sred[0] = ss;
    }
    __syncthreads();
    float inv = 1.f / sred[0];
    v.x *= inv; v.y *= inv; v.z *= inv; v.w *= inv;
    p[t] = v;
}

// ---------------------------------------------------------------------------
// Weighted mean of concat([var_y, yo]) over tokens  ->  g_cbar [B, 2H]
// ---------------------------------------------------------------------------
__global__ void k_cbar(const int* __restrict__ pp)
{
    int b = blockIdx.x;
    int c = blockIdx.y * 256 + threadIdx.x;   // 0..1535
    int t = threadIdx.x;
    __shared__ float wbuf[N_];
    __shared__ unsigned char sbuf[N_];
    __shared__ float wsumsh;
    for (int n = t; n < N_; n += 256) {
        int ppv = pp[b * N_ + n];
        bool pred   = (ppv == 1);
        bool single = (n == 0) || (n >= 2 && pp[b * N_ + n - 2] == 1);
        bool upper  = pred && (n <= 1 || !single);
        bool triple = upper && (n >= 1);
        wbuf[n] = pred ? (triple ? 3.f : 2.f) : 0.f;
        sbuf[n] = single ? 1 : 0;
    }
    __syncthreads();
    if (t == 0) { float s = 0.f; for (int n = 0; n < N_; n++) s += wbuf[n]; wsumsh = s; }
    __syncthreads();
    const float* Y = g_yo + (long long)b * N_ * H_;
    float acc = 0.f;
    if (c < H_) {
        for (int n = 0; n < N_; n++) {
            float w = wbuf[n]; if (w == 0.f) continue;
            float yn = Y[(long long)((n + 1) & (N_ - 1)) * H_ + c];
            float val = sbuf[n] ? yn
                                : 0.5f * (Y[(long long)((n - 1) & (N_ - 1)) * H_ + c] + yn);
            acc += w * val;
        }
    } else {
        int cc = c - H_;
        for (int n = 0; n < N_; n++) {
            float w = wbuf[n]; if (w == 0.f) continue;
            acc += w * Y[(long long)n * H_ + cc];
        }
    }
    g_cbar[b * H2_ + c] = acc / wsumsh;
}

// ---------------------------------------------------------------------------
// pm = cbar @ W_atom^T + b_atom   (tiny GEMM, one block per batch)
// ---------------------------------------------------------------------------
__global__ void k_pm(const float* __restrict__ Wa, const float* __restrict__ ba)
{
    int b = blockIdx.x;
    int t = threadIdx.x;                  // 768
    __shared__ float cb[H2_];
    for (int k = t; k < H2_; k += H_) cb[k] = g_cbar[b * H2_ + k];
    __syncthreads();
    const float* wr = Wa + (long long)t * H2_;
    float acc = 0.f;
    for (int k = 0; k < H2_; k++) acc += cb[k] * wr[k];
    g_pm[b * H_ + t] = acc + ba[t];
}

// ---------------------------------------------------------------------------
// Broadcast pm to output [B, N, H] (float4)
// ---------------------------------------------------------------------------
__global__ void k_bcast(float4* __restrict__ out)
{
    int idx = blockIdx.x * blockDim.x + threadIdx.x;
    if (idx >= B_ * N_ * H_ / 4) return;
    int h4 = idx % (H_ / 4);
    int b  = idx / (N_ * H_ / 4);
    out[idx] = reinterpret_cast<const float4*>(g_pm)[b * (H_ / 4) + h4];
}

// ---------------------------------------------------------------------------
// Launch
// ---------------------------------------------------------------------------
extern "C" void kernel_launch(void* const* d_in, const int* in_sizes, int n_in,
                              void* d_out, int out_size)
{
    const float* x       = (const float*)d_in[0];
    const float* ag_in   = (const float*)d_in[1];
    const float* vg_in   = (const float*)d_in[2];
    const float* W_var   = (const float*)d_in[3];  const float* b_var  = (const float*)d_in[4];
    const float* W_sym   = (const float*)d_in[5];  const float* b_sym  = (const float*)d_in[6];
    const float* W_score = (const float*)d_in[7];  const float* b_score= (const float*)d_in[8];
    const float* W_cross = (const float*)d_in[9];  const float* b_cross= (const float*)d_in[10];
    const float* W_atom  = (const float*)d_in[11]; const float* b_atom = (const float*)d_in[12];
    const float* W_q     = (const float*)d_in[13]; const float* b_q    = (const float*)d_in[14];
    const float* W_k     = (const float*)d_in[15]; const float* b_k    = (const float*)d_in[16];
    const float* W_v     = (const float*)d_in[17]; const float* b_v    = (const float*)d_in[18];
    const float* W_o     = (const float*)d_in[19]; const float* b_o    = (const float*)d_in[20];
    const int*   pp      = (const int*)d_in[21];
    const int*   occ     = (const int*)d_in[24];
    float* out = (float*)d_out;

    const int tot = B_ * N_ * H_;

    // var_in
    k_varin<<<(tot + 255) / 256, 256>>>(x, pp);

    // linear layers for edge scoring (tf32 tensor cores)
    dim3 gl(H_ / 128, (B_ * N_) / 128, 1);
    k_mma<OP_VAR, 128, 128, 32, 64, 64><<<gl, 128>>>(W_var, b_var, nullptr);
    k_mma<OP_SYM, 128, 128, 32, 64, 64><<<gl, 128>>>(W_sym, b_sym, x);
    k_score<<<B_ * N_, 256>>>(W_score, b_score);

    // graphs
    k_copy2<<<(B_ * N_ * N_ / 4 + 255) / 256, 256>>>(
        (const float4*)ag_in, (const float4*)vg_in);
    k_scatterAG<<<(B_ * N_ + 255) / 256, 256>>>(pp);
    k_cross<<<B_ * MO_, 256>>>(x, W_cross, b_cross, occ);

    // q, k, v projections
    k_mma<OP_Q, 128, 128, 32, 64, 64><<<gl, 128>>>(W_q, b_q, x);
    k_mma<OP_K, 128, 128, 32, 64, 64><<<gl, 128>>>(W_k, b_k, x);
    k_mma<OP_V, 128, 128, 32, 64, 64><<<gl, 128>>>(W_v, b_v, x);

    // BIAS = 0.2*AG + 0.8*AG@AG ; BIAS += VG@VG
    dim3 gg(N_ / 128, N_ / 128, B_);
    k_mma<OP_AGAG, 128, 128, 32, 64, 64><<<gg, 128>>>(nullptr, nullptr, nullptr);
    k_mma<OP_VGVG, 128, 128, 32, 64, 64><<<gg, 128>>>(nullptr, nullptr, nullptr);

    // attention logits, softmax, PV
    dim3 gs(N_ / 128, N_ / 128, B_ * NH_);
    k_mma<OP_SC, 128, 128, 32, 64, 64><<<gs, 128>>>(nullptr, nullptr, nullptr);
    k_softmax<<<B_ * NH_ * N_, 256>>>();
    dim3 gp(1, N_ / 128, B_ * NH_);
    k_mma<OP_PV, 128, 64, 32, 64, 32><<<gp, 128>>>(nullptr, nullptr, nullptr);

    // output projection
    k_mma<OP_O, 128, 128, 32, 64, 64><<<gl, 128>>>(W_o, b_o, nullptr);

    // path embedding (affine trick: weighted-mean before W_atom)
    dim3 gc(B_, H2_ / 256);
    k_cbar<<<gc, 256>>>(pp);
    k_pm<<<B_, H_>>>(W_atom, b_atom);
    k_bcast<<<(tot / 4 + 255) / 256, 256>>>((float4*)out);
}